// round 14
// baseline (speedup 1.0000x reference)
#include <cuda_runtime.h>
#include <cuda_bf16.h>
#include <math.h>

// Problem constants (fixed by the reference)
#define F_IN 503
#define CC   32
#define MAXN 100000
#define MAXE 3200000
#define GROWS 128     // rows per GEMM block (8 warps x m16)
#define BST  536      // B smem row stride in bf16 (1072B: LDSM conflict-free)
#define NEG  0.2f

// ---------------- scratch (static __device__ arrays; allocation-free) -------
__device__ float g_xl[(size_t)MAXN * CC];     // transformed node features [N,32]
__device__ float g_asrc[MAXN];
__device__ float g_adst[MAXN];
__device__ int   g_deg[MAXN];                 // in-degree (real edges only)
__device__ int   g_scan[MAXN];
__device__ int   g_rowptr[MAXN + 1];
__device__ int   g_cursor[MAXN];
__device__ int   g_bsum[256];
__device__ int   g_boff[256];
__device__ unsigned long long g_csr[MAXE + MAXN];   // packed (src:int, w:float)
__device__ float g_hw[MAXN];                  // h[v] . Ww
__device__ float g_scalars[4];   // [0]=sum(ew), [1]=k_edge, [2]=mean(ew)

// ---------------- init: deg=0, scalars --------------------------------------
__global__ void k_init(const float* __restrict__ W_edge,
                       const float* __restrict__ att_edge, int nN) {
    int i = blockIdx.x * blockDim.x + threadIdx.x;
    if (i < nN) g_deg[i] = 0;
    if (i == 0) {
        g_scalars[0] = 0.f;
        float ke = 0.f;
        #pragma unroll
        for (int c = 0; c < CC; c++) ke += W_edge[c] * att_edge[c];
        g_scalars[1] = ke;   // a_edge = k_edge * edge_weight
    }
}

// ---------------- degree count + edge_weight sum (vectorized) ---------------
__global__ void k_deg_mean(const int* __restrict__ ei,
                           const float* __restrict__ ew, int nE) {
    int tid = threadIdx.x;
    float sum = 0.f;
    int nq = nE >> 2;
    for (int q = blockIdx.x * blockDim.x + tid; q < nq;
         q += gridDim.x * blockDim.x) {
        int4 d4 = ((const int4*)(ei + nE))[q];
        float4 w4 = ((const float4*)ew)[q];
        atomicAdd(&g_deg[d4.x], 1);
        atomicAdd(&g_deg[d4.y], 1);
        atomicAdd(&g_deg[d4.z], 1);
        atomicAdd(&g_deg[d4.w], 1);
        sum += w4.x + w4.y + w4.z + w4.w;
    }
    int base = nq << 2;
    for (int i = base + blockIdx.x * blockDim.x + tid; i < nE;
         i += gridDim.x * blockDim.x) {
        atomicAdd(&g_deg[ei[nE + i]], 1);
        sum += ew[i];
    }
    __shared__ float red[256];
    red[tid] = sum;
    __syncthreads();
    for (int s = 128; s > 0; s >>= 1) {
        if (tid < s) red[tid] += red[tid + s];
        __syncthreads();
    }
    if (tid == 0) atomicAdd(&g_scalars[0], red[0]);
}

// ---------------- helpers ----------------------------------------------------
__device__ __forceinline__ void mma16816(float* c,
                                         unsigned a0, unsigned a1,
                                         unsigned a2, unsigned a3,
                                         unsigned b0, unsigned b1) {
    asm volatile(
        "mma.sync.aligned.m16n8k16.row.col.f32.bf16.bf16.f32 "
        "{%0,%1,%2,%3}, {%4,%5,%6,%7}, {%8,%9}, {%0,%1,%2,%3};"
        : "+f"(c[0]), "+f"(c[1]), "+f"(c[2]), "+f"(c[3])
        : "r"(a0), "r"(a1), "r"(a2), "r"(a3), "r"(b0), "r"(b1));
}

#define LDSM4(r0, r1, r2, r3, addr)                                        \
    asm volatile("ldmatrix.sync.aligned.m8n8.x4.shared.b16 "               \
                 "{%0,%1,%2,%3}, [%4];"                                    \
                 : "=r"(r0), "=r"(r1), "=r"(r2), "=r"(r3) : "r"(addr))

__device__ __forceinline__ void bsplit(float v0, float v1,
                                       unsigned& h, unsigned& l) {
    __nv_bfloat16 h0 = __float2bfloat16(v0);
    __nv_bfloat16 h1 = __float2bfloat16(v1);
    float r0 = v0 - __bfloat162float(h0);
    float r1 = v1 - __bfloat162float(h1);
    __nv_bfloat162 hh = __halves2bfloat162(h0, h1);
    __nv_bfloat162 ll = __halves2bfloat162(__float2bfloat16(r0),
                                           __float2bfloat16(r1));
    h = *(unsigned*)&hh;
    l = *(unsigned*)&ll;
}

// ---------------- GEMM: xl = x @ W^T via bf16-split tensor cores ------------
// A fragments loaded DIRECTLY from global (each x element read once,
// sector-coalesced across the lane quads) and split hi/lo in registers.
// W staged once per block into smem (hi+lo, LDSM-conflict-free stride) and
// read with ldmatrix.x4. No __syncthreads in the k-loop.
__global__ void __launch_bounds__(256, 3)
k_gemm(const float* __restrict__ x, const float* __restrict__ W,
       const float* __restrict__ att_src, const float* __restrict__ att_dst,
       int nN) {
    extern __shared__ __nv_bfloat16 bsm[];
    __nv_bfloat16* Bh = bsm;                 // [32][BST]
    __nv_bfloat16* Bl = bsm + 32 * BST;

    int tid = threadIdx.x;
    int lane = tid & 31;
    int wid = tid >> 5;
    int rbase = blockIdx.x * GROWS;

    // ---- stage all of W (hi/lo split), once ----
    for (int i = tid; i < 32 * 256; i += 256) {
        int n = i >> 8;
        int k = (i & 255) << 1;
        float w0 = (k < F_IN) ? W[n * F_IN + k] : 0.f;
        float w1 = (k + 1 < F_IN) ? W[n * F_IN + k + 1] : 0.f;
        unsigned h, l;
        bsplit(w0, w1, h, l);
        *(unsigned*)&Bh[n * BST + k] = h;
        *(unsigned*)&Bl[n * BST + k] = l;
    }
    __syncthreads();

    // fragment coordinates (PTX m16n8k16 mapping)
    int grp = lane >> 2;               // groupID (0..7)
    int qid = lane & 3;                // thread-in-group
    int frow = wid * 16 + grp;         // local A rows frow, frow+8
    int kp = qid * 2;

    int row0 = rbase + frow;
    int row1 = row0 + 8;
    const float* rp0 = x + (size_t)min(row0, nN - 1) * F_IN;
    const float* rp1 = x + (size_t)min(row1, nN - 1) * F_IN;

    // ldmatrix lane->address: lanes 0-7 m0, 8-15 m1, 16-23 m2, 24-31 m3
    // m0=[n0-7][k0-7] m1=[n0-7][k8-15] m2=[n8-15][k0-7] m3=[n8-15][k8-15]
    int mrow = (lane & 7) + ((lane >> 4) << 3);
    int mcol = ((lane >> 3) & 1) << 3;
    unsigned bh_a = (unsigned)__cvta_generic_to_shared(&Bh[mrow * BST + mcol]);
    unsigned bl_a = (unsigned)__cvta_generic_to_shared(&Bl[mrow * BST + mcol]);
    const unsigned half2off = 16 * BST * 2;   // bytes to n-rows 16-31

    float c[4][4];
    #pragma unroll
    for (int nt = 0; nt < 4; nt++)
        #pragma unroll
        for (int j = 0; j < 4; j++) c[nt][j] = 0.f;

    #pragma unroll 2
    for (int kt = 0; kt < 512; kt += 16) {
        // ---- A fragments from global, hi/lo split ----
        unsigned ah[4], al[4];
        if (kt < 496) {
            bsplit(rp0[kt + kp],     rp0[kt + kp + 1], ah[0], al[0]);
            bsplit(rp1[kt + kp],     rp1[kt + kp + 1], ah[1], al[1]);
            bsplit(rp0[kt + kp + 8], rp0[kt + kp + 9], ah[2], al[2]);
            bsplit(rp1[kt + kp + 8], rp1[kt + kp + 9], ah[3], al[3]);
        } else {
            int k0 = kt + kp, k1 = kt + kp + 8;
            float a = (k0 < F_IN) ? rp0[k0] : 0.f;
            float b = (k0 + 1 < F_IN) ? rp0[k0 + 1] : 0.f;
            bsplit(a, b, ah[0], al[0]);
            a = (k0 < F_IN) ? rp1[k0] : 0.f;
            b = (k0 + 1 < F_IN) ? rp1[k0 + 1] : 0.f;
            bsplit(a, b, ah[1], al[1]);
            a = (k1 < F_IN) ? rp0[k1] : 0.f;
            b = (k1 + 1 < F_IN) ? rp0[k1 + 1] : 0.f;
            bsplit(a, b, ah[2], al[2]);
            a = (k1 < F_IN) ? rp1[k1] : 0.f;
            b = (k1 + 1 < F_IN) ? rp1[k1 + 1] : 0.f;
            bsplit(a, b, ah[3], al[3]);
        }

        // ---- B fragments via ldmatrix.x4 (ntiles 0,1 then 2,3) ----
        unsigned bh[8], bl[8];
        unsigned o = kt * 2;   // byte offset along k
        LDSM4(bh[0], bh[1], bh[2], bh[3], bh_a + o);
        LDSM4(bh[4], bh[5], bh[6], bh[7], bh_a + o + half2off);
        LDSM4(bl[0], bl[1], bl[2], bl[3], bl_a + o);
        LDSM4(bl[4], bl[5], bl[6], bl[7], bl_a + o + half2off);

        #pragma unroll
        for (int nt = 0; nt < 4; nt++) {
            mma16816(c[nt], ah[0], ah[1], ah[2], ah[3],
                     bh[nt * 2], bh[nt * 2 + 1]);
            mma16816(c[nt], ah[0], ah[1], ah[2], ah[3],
                     bl[nt * 2], bl[nt * 2 + 1]);
            mma16816(c[nt], al[0], al[1], al[2], al[3],
                     bh[nt * 2], bh[nt * 2 + 1]);
        }
    }

    // ---- epilogue: store xl, fused a_src/a_dst (intra-quad reduction) ----
    float as0 = 0.f, ad0 = 0.f, as1 = 0.f, ad1 = 0.f;
    #pragma unroll
    for (int nt = 0; nt < 4; nt++) {
        int ch = nt * 8 + qid * 2;
        float s0 = att_src[ch], s1 = att_src[ch + 1];
        float d0 = att_dst[ch], d1 = att_dst[ch + 1];
        if (row0 < nN)
            *(float2*)&g_xl[(size_t)row0 * CC + ch] =
                make_float2(c[nt][0], c[nt][1]);
        if (row1 < nN)
            *(float2*)&g_xl[(size_t)row1 * CC + ch] =
                make_float2(c[nt][2], c[nt][3]);
        as0 += c[nt][0] * s0 + c[nt][1] * s1;
        ad0 += c[nt][0] * d0 + c[nt][1] * d1;
        as1 += c[nt][2] * s0 + c[nt][3] * s1;
        ad1 += c[nt][2] * d0 + c[nt][3] * d1;
    }
    #pragma unroll
    for (int o = 1; o <= 2; o <<= 1) {
        as0 += __shfl_xor_sync(0xFFFFFFFFu, as0, o);
        ad0 += __shfl_xor_sync(0xFFFFFFFFu, ad0, o);
        as1 += __shfl_xor_sync(0xFFFFFFFFu, as1, o);
        ad1 += __shfl_xor_sync(0xFFFFFFFFu, ad1, o);
    }
    if (qid == 0) {
        if (row0 < nN) { g_asrc[row0] = as0; g_adst[row0] = ad0; }
        if (row1 < nN) { g_asrc[row1] = as1; g_adst[row1] = ad1; }
    }
}

// ---------------- scan (exclusive prefix of deg -> rowptr) ------------------
__global__ void k_scan1(int nN) {
    __shared__ int sh[1024];
    int tid = threadIdx.x;
    int i = blockIdx.x * 1024 + tid;
    int v = (i < nN) ? g_deg[i] : 0;
    sh[tid] = v;
    __syncthreads();
    for (int off = 1; off < 1024; off <<= 1) {
        int t = (tid >= off) ? sh[tid - off] : 0;
        __syncthreads();
        sh[tid] += t;
        __syncthreads();
    }
    if (i < nN) g_scan[i] = sh[tid];
    if (tid == 1023) g_bsum[blockIdx.x] = sh[1023];
}

__global__ void k_scan2(int nb, int nE) {
    int run = 0;
    for (int b = 0; b < nb; b++) {
        int t = g_bsum[b];
        g_boff[b] = run;
        run += t;
    }
    g_scalars[2] = g_scalars[0] / (float)nE;   // mean edge weight
}

// rowptr[i] = edge_scan[i] + i (self-loop slot per node, pre-written here).
__global__ void k_scan3(int nN, int nE) {
    int i = blockIdx.x * blockDim.x + threadIdx.x;
    if (i < nN) {
        int ex = g_scan[i] - g_deg[i] + g_boff[i >> 10] + i;
        g_rowptr[i] = ex;
        g_cursor[i] = ex + 1;
        unsigned long long e = (unsigned long long)(unsigned)i |
            ((unsigned long long)__float_as_uint(g_scalars[2]) << 32);
        g_csr[ex] = e;
    }
    if (i == 0) g_rowptr[nN] = nN + nE;
}

// ---------------- fill CSR with packed (src, edge_weight) -------------------
__global__ void k_fill(const int* __restrict__ ei, const float* __restrict__ ew,
                       int nE) {
    int i = blockIdx.x * blockDim.x + threadIdx.x;
    if (i >= nE) return;
    int s = ei[i];
    int d = ei[nE + i];
    float w = ew[i];
    int pos = atomicAdd(&g_cursor[d], 1);
    unsigned long long e = (unsigned long long)(unsigned)s |
                           ((unsigned long long)__float_as_uint(w) << 32);
    g_csr[pos] = e;
}

// ---------------- gather: softmax-aggregate + fused heads -------------------
__global__ void __launch_bounds__(256)
k_gather(const float* __restrict__ bias_conv,
         const float* __restrict__ Wb, const float* __restrict__ bb,
         const float* __restrict__ Ww, const float* __restrict__ mask,
         float* __restrict__ out, int nN, int nE) {
    int warp = (blockIdx.x * blockDim.x + threadIdx.x) >> 5;
    int lane = threadIdx.x & 31;
    if (warp >= nN) return;
    int beg = g_rowptr[warp];
    int end = g_rowptr[warp + 1];
    float ad = g_adst[warp];
    float ke = g_scalars[1];
    float acc = 0.f, den = 0.f;

    int i = beg;
    for (; i + 4 <= end; i += 4) {
        unsigned long long e0 = g_csr[i];
        unsigned long long e1 = g_csr[i + 1];
        unsigned long long e2 = g_csr[i + 2];
        unsigned long long e3 = g_csr[i + 3];
        int s0 = (int)(unsigned)e0, s1 = (int)(unsigned)e1;
        int s2 = (int)(unsigned)e2, s3 = (int)(unsigned)e3;
        float v0 = g_xl[(size_t)s0 * CC + lane];
        float v1 = g_xl[(size_t)s1 * CC + lane];
        float v2 = g_xl[(size_t)s2 * CC + lane];
        float v3 = g_xl[(size_t)s3 * CC + lane];
        float as0 = g_asrc[s0], as1 = g_asrc[s1];
        float as2 = g_asrc[s2], as3 = g_asrc[s3];
        float a0 = fmaf(ke, __uint_as_float((unsigned)(e0 >> 32)), as0 + ad);
        float a1 = fmaf(ke, __uint_as_float((unsigned)(e1 >> 32)), as1 + ad);
        float a2 = fmaf(ke, __uint_as_float((unsigned)(e2 >> 32)), as2 + ad);
        float a3 = fmaf(ke, __uint_as_float((unsigned)(e3 >> 32)), as3 + ad);
        a0 = (a0 > 0.f) ? a0 : NEG * a0;
        a1 = (a1 > 0.f) ? a1 : NEG * a1;
        a2 = (a2 > 0.f) ? a2 : NEG * a2;
        a3 = (a3 > 0.f) ? a3 : NEG * a3;
        float x0 = __expf(a0), x1 = __expf(a1);
        float x2 = __expf(a2), x3 = __expf(a3);
        den += x0 + x1 + x2 + x3;
        acc = fmaf(x0, v0, acc);
        acc = fmaf(x1, v1, acc);
        acc = fmaf(x2, v2, acc);
        acc = fmaf(x3, v3, acc);
    }
    for (; i < end; i++) {
        unsigned long long e = g_csr[i];
        int s = (int)(unsigned)e;
        float v = g_xl[(size_t)s * CC + lane];
        float a = fmaf(ke, __uint_as_float((unsigned)(e >> 32)), g_asrc[s] + ad);
        a = (a > 0.f) ? a : NEG * a;
        float ex = __expf(a);
        den += ex;
        acc = fmaf(ex, v, acc);
    }

    float h = acc / den + bias_conv[lane];
    h = fmaxf(h, 0.f);
    float bsum = h * Wb[lane];
    float wsum = h * Ww[lane];
    #pragma unroll
    for (int o = 16; o > 0; o >>= 1) {
        bsum += __shfl_xor_sync(0xFFFFFFFFu, bsum, o);
        wsum += __shfl_xor_sync(0xFFFFFFFFu, wsum, o);
    }
    if (lane == 0) {
        g_hw[warp] = wsum;
        out[nE + warp] = (bsum + bb[0]) * mask[warp];
    }
}

// ---------------- edge output: 0.5*(hw[s]+hw[d]) + bw (vectorized) ---------
__global__ void k_edge(const int* __restrict__ ei, const float* __restrict__ bw,
                       float* __restrict__ out, int nE) {
    int q = blockIdx.x * blockDim.x + threadIdx.x;
    int nq = nE >> 2;
    float b = bw[0];
    if (q < nq) {
        int4 s4 = ((const int4*)ei)[q];
        int4 d4 = ((const int4*)(ei + nE))[q];
        float4 o;
        o.x = 0.5f * (g_hw[s4.x] + g_hw[d4.x]) + b;
        o.y = 0.5f * (g_hw[s4.y] + g_hw[d4.y]) + b;
        o.z = 0.5f * (g_hw[s4.z] + g_hw[d4.z]) + b;
        o.w = 0.5f * (g_hw[s4.w] + g_hw[d4.w]) + b;
        ((float4*)out)[q] = o;
    }
    if (q < (nE & 3)) {
        int idx = (nq << 2) + q;
        out[idx] = 0.5f * (g_hw[ei[idx]] + g_hw[ei[nE + idx]]) + b;
    }
}

// ---------------- launch ----------------------------------------------------
extern "C" void kernel_launch(void* const* d_in, const int* in_sizes, int n_in,
                              void* d_out, int out_size) {
    const float* x         = (const float*)d_in[0];
    const int*   ei        = (const int*)d_in[1];
    const float* ew        = (const float*)d_in[2];
    const float* mask      = (const float*)d_in[3];
    const float* W_src     = (const float*)d_in[4];
    const float* att_src   = (const float*)d_in[5];
    const float* att_dst   = (const float*)d_in[6];
    const float* att_edge  = (const float*)d_in[7];
    const float* W_edge    = (const float*)d_in[8];
    const float* bias_conv = (const float*)d_in[9];
    const float* Wb        = (const float*)d_in[10];
    const float* bb        = (const float*)d_in[11];
    const float* Ww        = (const float*)d_in[12];
    const float* bw        = (const float*)d_in[13];
    float* out = (float*)d_out;

    int nN = in_sizes[3];            // input_mask: [N,1]
    int nE = in_sizes[2];            // edge_weight: [E,1]

    const int bsmem = 2 * 32 * BST * 2;   // 68608 B
    cudaFuncSetAttribute((const void*)k_gemm,
                         cudaFuncAttributeMaxDynamicSharedMemorySize, bsmem);

    int nb = (nN + 1023) / 1024;
    // Order keeps k_gemm in the ncu-profiled slot (4th launch).
    k_init<<<(nN + 255) / 256, 256>>>(W_edge, att_edge, nN);
    k_deg_mean<<<2048, 256>>>(ei, ew, nE);
    k_scan1<<<nb, 1024>>>(nN);
    k_gemm<<<(nN + GROWS - 1) / GROWS, 256, bsmem>>>(x, W_src, att_src,
                                                     att_dst, nN);
    k_scan2<<<1, 1>>>(nb, nE);
    k_scan3<<<(nN + 255) / 256, 256>>>(nN, nE);
    k_fill<<<(nE + 255) / 256, 256>>>(ei, ew, nE);
    k_gather<<<(nN + 7) / 8, 256>>>(bias_conv, Wb, bb, Ww, mask, out, nN, nE);
    k_edge<<<((nE >> 2) + 255) / 256, 256>>>(ei, bw, out, nE);
}

// round 15
// speedup vs baseline: 1.0407x; 1.0407x over previous
#include <cuda_runtime.h>
#include <cuda_bf16.h>
#include <math.h>

// Problem constants (fixed by the reference)
#define F_IN 503
#define CC   32
#define MAXN 100000
#define MAXE 3200000
#define GROWS 128     // rows per GEMM block (8 warps x m16)
#define BST  536      // B smem row stride in bf16 (1072B: LDSM conflict-free)
#define NEG  0.2f

// ---------------- scratch (static __device__ arrays; allocation-free) -------
__device__ float g_xl[(size_t)MAXN * CC];     // transformed node features [N,32]
__device__ float g_asrc[MAXN];
__device__ float g_adst[MAXN];
__device__ int   g_deg[MAXN];                 // in-degree (real edges only)
__device__ int   g_scan[MAXN];
__device__ int   g_rowptr[MAXN + 1];
__device__ int   g_cursor[MAXN];
__device__ int   g_bsum[256];
__device__ int   g_boff[256];
__device__ unsigned long long g_csr[MAXE + MAXN];   // packed (src:int, w:float)
__device__ float g_hw[MAXN];                  // h[v] . Ww
__device__ float g_scalars[4];   // [0]=sum(ew), [1]=k_edge, [2]=mean(ew)

// ---------------- init: deg=0, scalars --------------------------------------
__global__ void k_init(const float* __restrict__ W_edge,
                       const float* __restrict__ att_edge, int nN) {
    int i = blockIdx.x * blockDim.x + threadIdx.x;
    if (i < nN) g_deg[i] = 0;
    if (i == 0) {
        g_scalars[0] = 0.f;
        float ke = 0.f;
        #pragma unroll
        for (int c = 0; c < CC; c++) ke += W_edge[c] * att_edge[c];
        g_scalars[1] = ke;   // a_edge = k_edge * edge_weight
    }
}

// ---------------- degree count + edge_weight sum (vectorized) ---------------
__global__ void k_deg_mean(const int* __restrict__ ei,
                           const float* __restrict__ ew, int nE) {
    int tid = threadIdx.x;
    float sum = 0.f;
    int nq = nE >> 2;
    for (int q = blockIdx.x * blockDim.x + tid; q < nq;
         q += gridDim.x * blockDim.x) {
        int4 d4 = ((const int4*)(ei + nE))[q];
        float4 w4 = ((const float4*)ew)[q];
        atomicAdd(&g_deg[d4.x], 1);
        atomicAdd(&g_deg[d4.y], 1);
        atomicAdd(&g_deg[d4.z], 1);
        atomicAdd(&g_deg[d4.w], 1);
        sum += w4.x + w4.y + w4.z + w4.w;
    }
    int base = nq << 2;
    for (int i = base + blockIdx.x * blockDim.x + tid; i < nE;
         i += gridDim.x * blockDim.x) {
        atomicAdd(&g_deg[ei[nE + i]], 1);
        sum += ew[i];
    }
    __shared__ float red[256];
    red[tid] = sum;
    __syncthreads();
    for (int s = 128; s > 0; s >>= 1) {
        if (tid < s) red[tid] += red[tid + s];
        __syncthreads();
    }
    if (tid == 0) atomicAdd(&g_scalars[0], red[0]);
}

// ---------------- helpers ----------------------------------------------------
__device__ __forceinline__ void mma16816(float* c,
                                         unsigned a0, unsigned a1,
                                         unsigned a2, unsigned a3,
                                         unsigned b0, unsigned b1) {
    asm volatile(
        "mma.sync.aligned.m16n8k16.row.col.f32.bf16.bf16.f32 "
        "{%0,%1,%2,%3}, {%4,%5,%6,%7}, {%8,%9}, {%0,%1,%2,%3};"
        : "+f"(c[0]), "+f"(c[1]), "+f"(c[2]), "+f"(c[3])
        : "r"(a0), "r"(a1), "r"(a2), "r"(a3), "r"(b0), "r"(b1));
}

#define LDSM4(r0, r1, r2, r3, addr)                                        \
    asm volatile("ldmatrix.sync.aligned.m8n8.x4.shared.b16 "               \
                 "{%0,%1,%2,%3}, [%4];"                                    \
                 : "=r"(r0), "=r"(r1), "=r"(r2), "=r"(r3) : "r"(addr))

// Cheap split: hi = truncate-to-bf16 (PRMT pack), lo = round(v - hi).
// |err| ~ 2^-16 relative — far inside the 1e-3 budget.
__device__ __forceinline__ void bsplit2(float v0, float v1,
                                        unsigned& h, unsigned& l) {
    unsigned u0 = __float_as_uint(v0);
    unsigned u1 = __float_as_uint(v1);
    h = __byte_perm(u0, u1, 0x7632);           // {hi16(u0), hi16(u1)}
    float l0 = v0 - __uint_as_float(u0 & 0xFFFF0000u);
    float l1 = v1 - __uint_as_float(u1 & 0xFFFF0000u);
    asm("cvt.rn.bf16x2.f32 %0, %1, %2;" : "=r"(l) : "f"(l1), "f"(l0));
}

// ---------------- GEMM: xl = x @ W^T via bf16-split tensor cores ------------
// A loaded directly from global with a ONE-TILE REGISTER PREFETCH: tile k+1's
// 8 independent LDG.32 issue before tile k's cvt+mma block, so load latency
// overlaps compute. W staged once per block in smem, read via ldmatrix.x4.
// No __syncthreads in the k-loop.
__global__ void __launch_bounds__(256, 3)
k_gemm(const float* __restrict__ x, const float* __restrict__ W,
       const float* __restrict__ att_src, const float* __restrict__ att_dst,
       int nN) {
    extern __shared__ __nv_bfloat16 bsm[];
    __nv_bfloat16* Bh = bsm;                 // [32][BST]
    __nv_bfloat16* Bl = bsm + 32 * BST;

    int tid = threadIdx.x;
    int lane = tid & 31;
    int wid = tid >> 5;
    int rbase = blockIdx.x * GROWS;

    // ---- stage all of W (hi/lo split), once ----
    for (int i = tid; i < 32 * 256; i += 256) {
        int n = i >> 8;
        int k = (i & 255) << 1;
        float w0 = (k < F_IN) ? W[n * F_IN + k] : 0.f;
        float w1 = (k + 1 < F_IN) ? W[n * F_IN + k + 1] : 0.f;
        unsigned h, l;
        bsplit2(w0, w1, h, l);
        *(unsigned*)&Bh[n * BST + k] = h;
        *(unsigned*)&Bl[n * BST + k] = l;
    }
    __syncthreads();

    // fragment coordinates (PTX m16n8k16 mapping)
    int grp = lane >> 2;               // groupID (0..7)
    int qid = lane & 3;                // thread-in-group
    int frow = wid * 16 + grp;         // local A rows frow, frow+8
    int kp = qid * 2;

    int row0 = rbase + frow;
    int row1 = row0 + 8;
    const float* rp0 = x + (size_t)min(row0, nN - 1) * F_IN + kp;
    const float* rp1 = x + (size_t)min(row1, nN - 1) * F_IN + kp;

    // ldmatrix lane->address mapping
    int mrow = (lane & 7) + ((lane >> 4) << 3);
    int mcol = ((lane >> 3) & 1) << 3;
    unsigned bh_a = (unsigned)__cvta_generic_to_shared(&Bh[mrow * BST + mcol]);
    unsigned bl_a = (unsigned)__cvta_generic_to_shared(&Bl[mrow * BST + mcol]);
    const unsigned half2off = 16 * BST * 2;   // bytes to n-rows 16-31

    float c[4][4];
    #pragma unroll
    for (int nt = 0; nt < 4; nt++)
        #pragma unroll
        for (int j = 0; j < 4; j++) c[nt][j] = 0.f;

    // A-tile loader: v = {r0:k,k+1, r1:k,k+1, r0:k+8,k+9, r1:k+8,k+9}
    auto loadA = [&](int kt, float* v) {
        if (kt < 496) {
            v[0] = rp0[kt];     v[1] = rp0[kt + 1];
            v[2] = rp1[kt];     v[3] = rp1[kt + 1];
            v[4] = rp0[kt + 8]; v[5] = rp0[kt + 9];
            v[6] = rp1[kt + 8]; v[7] = rp1[kt + 9];
        } else {
            int k0 = kt + kp, k1 = kt + kp + 8;
            v[0] = (k0 < F_IN)     ? rp0[kt]     : 0.f;
            v[1] = (k0 + 1 < F_IN) ? rp0[kt + 1] : 0.f;
            v[2] = (k0 < F_IN)     ? rp1[kt]     : 0.f;
            v[3] = (k0 + 1 < F_IN) ? rp1[kt + 1] : 0.f;
            v[4] = (k1 < F_IN)     ? rp0[kt + 8] : 0.f;
            v[5] = (k1 + 1 < F_IN) ? rp0[kt + 9] : 0.f;
            v[6] = (k1 < F_IN)     ? rp1[kt + 8] : 0.f;
            v[7] = (k1 + 1 < F_IN) ? rp1[kt + 9] : 0.f;
        }
    };

    float cur[8];
    loadA(0, cur);

    #pragma unroll 4
    for (int kt = 0; kt < 512; kt += 16) {
        // ---- B fragments via ldmatrix.x4 (independent of A chain) ----
        unsigned bh[8], bl[8];
        unsigned o = kt * 2;
        LDSM4(bh[0], bh[1], bh[2], bh[3], bh_a + o);
        LDSM4(bh[4], bh[5], bh[6], bh[7], bh_a + o + half2off);
        LDSM4(bl[0], bl[1], bl[2], bl[3], bl_a + o);
        LDSM4(bl[4], bl[5], bl[6], bl[7], bl_a + o + half2off);

        // ---- prefetch NEXT A tile (8 independent LDG.32) ----
        float nxt[8];
        if (kt < 496) loadA(kt + 16, nxt);

        // ---- split current A tile ----
        unsigned ah[4], al[4];
        bsplit2(cur[0], cur[1], ah[0], al[0]);
        bsplit2(cur[2], cur[3], ah[1], al[1]);
        bsplit2(cur[4], cur[5], ah[2], al[2]);
        bsplit2(cur[6], cur[7], ah[3], al[3]);

        #pragma unroll
        for (int nt = 0; nt < 4; nt++) {
            mma16816(c[nt], ah[0], ah[1], ah[2], ah[3],
                     bh[nt * 2], bh[nt * 2 + 1]);
            mma16816(c[nt], ah[0], ah[1], ah[2], ah[3],
                     bl[nt * 2], bl[nt * 2 + 1]);
            mma16816(c[nt], al[0], al[1], al[2], al[3],
                     bh[nt * 2], bh[nt * 2 + 1]);
        }

        if (kt < 496) {
            #pragma unroll
            for (int j = 0; j < 8; j++) cur[j] = nxt[j];
        }
    }

    // ---- epilogue: store xl, fused a_src/a_dst (intra-quad reduction) ----
    float as0 = 0.f, ad0 = 0.f, as1 = 0.f, ad1 = 0.f;
    #pragma unroll
    for (int nt = 0; nt < 4; nt++) {
        int ch = nt * 8 + qid * 2;
        float s0 = att_src[ch], s1 = att_src[ch + 1];
        float d0 = att_dst[ch], d1 = att_dst[ch + 1];
        if (row0 < nN)
            *(float2*)&g_xl[(size_t)row0 * CC + ch] =
                make_float2(c[nt][0], c[nt][1]);
        if (row1 < nN)
            *(float2*)&g_xl[(size_t)row1 * CC + ch] =
                make_float2(c[nt][2], c[nt][3]);
        as0 += c[nt][0] * s0 + c[nt][1] * s1;
        ad0 += c[nt][0] * d0 + c[nt][1] * d1;
        as1 += c[nt][2] * s0 + c[nt][3] * s1;
        ad1 += c[nt][2] * d0 + c[nt][3] * d1;
    }
    #pragma unroll
    for (int o = 1; o <= 2; o <<= 1) {
        as0 += __shfl_xor_sync(0xFFFFFFFFu, as0, o);
        ad0 += __shfl_xor_sync(0xFFFFFFFFu, ad0, o);
        as1 += __shfl_xor_sync(0xFFFFFFFFu, as1, o);
        ad1 += __shfl_xor_sync(0xFFFFFFFFu, ad1, o);
    }
    if (qid == 0) {
        if (row0 < nN) { g_asrc[row0] = as0; g_adst[row0] = ad0; }
        if (row1 < nN) { g_asrc[row1] = as1; g_adst[row1] = ad1; }
    }
}

// ---------------- scan (exclusive prefix of deg -> rowptr) ------------------
__global__ void k_scan1(int nN) {
    __shared__ int sh[1024];
    int tid = threadIdx.x;
    int i = blockIdx.x * 1024 + tid;
    int v = (i < nN) ? g_deg[i] : 0;
    sh[tid] = v;
    __syncthreads();
    for (int off = 1; off < 1024; off <<= 1) {
        int t = (tid >= off) ? sh[tid - off] : 0;
        __syncthreads();
        sh[tid] += t;
        __syncthreads();
    }
    if (i < nN) g_scan[i] = sh[tid];
    if (tid == 1023) g_bsum[blockIdx.x] = sh[1023];
}

__global__ void k_scan2(int nb, int nE) {
    int run = 0;
    for (int b = 0; b < nb; b++) {
        int t = g_bsum[b];
        g_boff[b] = run;
        run += t;
    }
    g_scalars[2] = g_scalars[0] / (float)nE;   // mean edge weight
}

// rowptr[i] = edge_scan[i] + i (self-loop slot per node, pre-written here).
__global__ void k_scan3(int nN, int nE) {
    int i = blockIdx.x * blockDim.x + threadIdx.x;
    if (i < nN) {
        int ex = g_scan[i] - g_deg[i] + g_boff[i >> 10] + i;
        g_rowptr[i] = ex;
        g_cursor[i] = ex + 1;
        unsigned long long e = (unsigned long long)(unsigned)i |
            ((unsigned long long)__float_as_uint(g_scalars[2]) << 32);
        g_csr[ex] = e;
    }
    if (i == 0) g_rowptr[nN] = nN + nE;
}

// ---------------- fill CSR with packed (src, edge_weight) -------------------
__global__ void k_fill(const int* __restrict__ ei, const float* __restrict__ ew,
                       int nE) {
    int i = blockIdx.x * blockDim.x + threadIdx.x;
    if (i >= nE) return;
    int s = ei[i];
    int d = ei[nE + i];
    float w = ew[i];
    int pos = atomicAdd(&g_cursor[d], 1);
    unsigned long long e = (unsigned long long)(unsigned)s |
                           ((unsigned long long)__float_as_uint(w) << 32);
    g_csr[pos] = e;
}

// ---------------- gather: softmax-aggregate + fused heads -------------------
__global__ void __launch_bounds__(256)
k_gather(const float* __restrict__ bias_conv,
         const float* __restrict__ Wb, const float* __restrict__ bb,
         const float* __restrict__ Ww, const float* __restrict__ mask,
         float* __restrict__ out, int nN, int nE) {
    int warp = (blockIdx.x * blockDim.x + threadIdx.x) >> 5;
    int lane = threadIdx.x & 31;
    if (warp >= nN) return;
    int beg = g_rowptr[warp];
    int end = g_rowptr[warp + 1];
    float ad = g_adst[warp];
    float ke = g_scalars[1];
    float acc = 0.f, den = 0.f;

    int i = beg;
    for (; i + 4 <= end; i += 4) {
        unsigned long long e0 = g_csr[i];
        unsigned long long e1 = g_csr[i + 1];
        unsigned long long e2 = g_csr[i + 2];
        unsigned long long e3 = g_csr[i + 3];
        int s0 = (int)(unsigned)e0, s1 = (int)(unsigned)e1;
        int s2 = (int)(unsigned)e2, s3 = (int)(unsigned)e3;
        float v0 = g_xl[(size_t)s0 * CC + lane];
        float v1 = g_xl[(size_t)s1 * CC + lane];
        float v2 = g_xl[(size_t)s2 * CC + lane];
        float v3 = g_xl[(size_t)s3 * CC + lane];
        float as0 = g_asrc[s0], as1 = g_asrc[s1];
        float as2 = g_asrc[s2], as3 = g_asrc[s3];
        float a0 = fmaf(ke, __uint_as_float((unsigned)(e0 >> 32)), as0 + ad);
        float a1 = fmaf(ke, __uint_as_float((unsigned)(e1 >> 32)), as1 + ad);
        float a2 = fmaf(ke, __uint_as_float((unsigned)(e2 >> 32)), as2 + ad);
        float a3 = fmaf(ke, __uint_as_float((unsigned)(e3 >> 32)), as3 + ad);
        a0 = (a0 > 0.f) ? a0 : NEG * a0;
        a1 = (a1 > 0.f) ? a1 : NEG * a1;
        a2 = (a2 > 0.f) ? a2 : NEG * a2;
        a3 = (a3 > 0.f) ? a3 : NEG * a3;
        float x0 = __expf(a0), x1 = __expf(a1);
        float x2 = __expf(a2), x3 = __expf(a3);
        den += x0 + x1 + x2 + x3;
        acc = fmaf(x0, v0, acc);
        acc = fmaf(x1, v1, acc);
        acc = fmaf(x2, v2, acc);
        acc = fmaf(x3, v3, acc);
    }
    for (; i < end; i++) {
        unsigned long long e = g_csr[i];
        int s = (int)(unsigned)e;
        float v = g_xl[(size_t)s * CC + lane];
        float a = fmaf(ke, __uint_as_float((unsigned)(e >> 32)), g_asrc[s] + ad);
        a = (a > 0.f) ? a : NEG * a;
        float ex = __expf(a);
        den += ex;
        acc = fmaf(ex, v, acc);
    }

    float h = acc / den + bias_conv[lane];
    h = fmaxf(h, 0.f);
    float bsum = h * Wb[lane];
    float wsum = h * Ww[lane];
    #pragma unroll
    for (int o = 16; o > 0; o >>= 1) {
        bsum += __shfl_xor_sync(0xFFFFFFFFu, bsum, o);
        wsum += __shfl_xor_sync(0xFFFFFFFFu, wsum, o);
    }
    if (lane == 0) {
        g_hw[warp] = wsum;
        out[nE + warp] = (bsum + bb[0]) * mask[warp];
    }
}

// ---------------- edge output: 0.5*(hw[s]+hw[d]) + bw (vectorized) ---------
__global__ void k_edge(const int* __restrict__ ei, const float* __restrict__ bw,
                       float* __restrict__ out, int nE) {
    int q = blockIdx.x * blockDim.x + threadIdx.x;
    int nq = nE >> 2;
    float b = bw[0];
    if (q < nq) {
        int4 s4 = ((const int4*)ei)[q];
        int4 d4 = ((const int4*)(ei + nE))[q];
        float4 o;
        o.x = 0.5f * (g_hw[s4.x] + g_hw[d4.x]) + b;
        o.y = 0.5f * (g_hw[s4.y] + g_hw[d4.y]) + b;
        o.z = 0.5f * (g_hw[s4.z] + g_hw[d4.z]) + b;
        o.w = 0.5f * (g_hw[s4.w] + g_hw[d4.w]) + b;
        ((float4*)out)[q] = o;
    }
    if (q < (nE & 3)) {
        int idx = (nq << 2) + q;
        out[idx] = 0.5f * (g_hw[ei[idx]] + g_hw[ei[nE + idx]]) + b;
    }
}

// ---------------- launch ----------------------------------------------------
extern "C" void kernel_launch(void* const* d_in, const int* in_sizes, int n_in,
                              void* d_out, int out_size) {
    const float* x         = (const float*)d_in[0];
    const int*   ei        = (const int*)d_in[1];
    const float* ew        = (const float*)d_in[2];
    const float* mask      = (const float*)d_in[3];
    const float* W_src     = (const float*)d_in[4];
    const float* att_src   = (const float*)d_in[5];
    const float* att_dst   = (const float*)d_in[6];
    const float* att_edge  = (const float*)d_in[7];
    const float* W_edge    = (const float*)d_in[8];
    const float* bias_conv = (const float*)d_in[9];
    const float* Wb        = (const float*)d_in[10];
    const float* bb        = (const float*)d_in[11];
    const float* Ww        = (const float*)d_in[12];
    const float* bw        = (const float*)d_in[13];
    float* out = (float*)d_out;

    int nN = in_sizes[3];            // input_mask: [N,1]
    int nE = in_sizes[2];            // edge_weight: [E,1]

    const int bsmem = 2 * 32 * BST * 2;   // 68608 B
    cudaFuncSetAttribute((const void*)k_gemm,
                         cudaFuncAttributeMaxDynamicSharedMemorySize, bsmem);

    int nb = (nN + 1023) / 1024;
    // Order keeps k_gemm in the ncu-profiled slot (4th launch).
    k_init<<<(nN + 255) / 256, 256>>>(W_edge, att_edge, nN);
    k_deg_mean<<<2048, 256>>>(ei, ew, nE);
    k_scan1<<<nb, 1024>>>(nN);
    k_gemm<<<(nN + GROWS - 1) / GROWS, 256, bsmem>>>(x, W_src, att_src,
                                                     att_dst, nN);
    k_scan2<<<1, 1>>>(nb, nE);
    k_scan3<<<(nN + 255) / 256, 256>>>(nN, nE);
    k_fill<<<(nE + 255) / 256, 256>>>(ei, ew, nE);
    k_gather<<<(nN + 7) / 8, 256>>>(bias_conv, Wb, bb, Ww, mask, out, nN, nE);
    k_edge<<<((nE >> 2) + 255) / 256, 256>>>(ei, bw, out, nE);
}

// round 16
// speedup vs baseline: 1.2239x; 1.1761x over previous
#include <cuda_runtime.h>
#include <cuda_bf16.h>
#include <math.h>

// Problem constants (fixed by the reference)
#define F_IN 503
#define CC   32
#define MAXN 100000
#define MAXE 3200000
#define GROWS 128     // rows per GEMM block (8 warps x m16)
#define BST  536      // B smem row stride in bf16 (1072B: LDSM conflict-free)
#define NEG  0.2f

// ---------------- scratch (static __device__ arrays; allocation-free) -------
__device__ float g_xl[(size_t)MAXN * CC];     // transformed node features [N,32]
__device__ float g_asrc[MAXN];
__device__ float g_adst[MAXN];
__device__ int   g_deg[MAXN];                 // in-degree (real edges only)
__device__ int   g_scan[MAXN];
__device__ int   g_rowptr[MAXN + 1];
__device__ int   g_cursor[MAXN];
__device__ int   g_bsum[256];
__device__ int   g_boff[256];
__device__ unsigned long long g_csr[MAXE + MAXN];   // packed (src:int, w:float)
__device__ float g_hw[MAXN];                  // h[v] . Ww
__device__ float g_scalars[4];   // [0]=sum(ew), [1]=k_edge, [2]=mean(ew)

// ---------------- init: deg=0, scalars --------------------------------------
__global__ void k_init(const float* __restrict__ W_edge,
                       const float* __restrict__ att_edge, int nN) {
    int i = blockIdx.x * blockDim.x + threadIdx.x;
    if (i < nN) g_deg[i] = 0;
    if (i == 0) {
        g_scalars[0] = 0.f;
        float ke = 0.f;
        #pragma unroll
        for (int c = 0; c < CC; c++) ke += W_edge[c] * att_edge[c];
        g_scalars[1] = ke;   // a_edge = k_edge * edge_weight
    }
}

// ---------------- degree count + edge_weight sum (vectorized) ---------------
__global__ void k_deg_mean(const int* __restrict__ ei,
                           const float* __restrict__ ew, int nE) {
    int tid = threadIdx.x;
    float sum = 0.f;
    int nq = nE >> 2;
    for (int q = blockIdx.x * blockDim.x + tid; q < nq;
         q += gridDim.x * blockDim.x) {
        int4 d4 = ((const int4*)(ei + nE))[q];
        float4 w4 = ((const float4*)ew)[q];
        atomicAdd(&g_deg[d4.x], 1);
        atomicAdd(&g_deg[d4.y], 1);
        atomicAdd(&g_deg[d4.z], 1);
        atomicAdd(&g_deg[d4.w], 1);
        sum += w4.x + w4.y + w4.z + w4.w;
    }
    int base = nq << 2;
    for (int i = base + blockIdx.x * blockDim.x + tid; i < nE;
         i += gridDim.x * blockDim.x) {
        atomicAdd(&g_deg[ei[nE + i]], 1);
        sum += ew[i];
    }
    __shared__ float red[256];
    red[tid] = sum;
    __syncthreads();
    for (int s = 128; s > 0; s >>= 1) {
        if (tid < s) red[tid] += red[tid + s];
        __syncthreads();
    }
    if (tid == 0) atomicAdd(&g_scalars[0], red[0]);
}

// ---------------- helpers ----------------------------------------------------
__device__ __forceinline__ void mma16816(float* c,
                                         unsigned a0, unsigned a1,
                                         unsigned a2, unsigned a3,
                                         unsigned b0, unsigned b1) {
    asm volatile(
        "mma.sync.aligned.m16n8k16.row.col.f32.bf16.bf16.f32 "
        "{%0,%1,%2,%3}, {%4,%5,%6,%7}, {%8,%9}, {%0,%1,%2,%3};"
        : "+f"(c[0]), "+f"(c[1]), "+f"(c[2]), "+f"(c[3])
        : "r"(a0), "r"(a1), "r"(a2), "r"(a3), "r"(b0), "r"(b1));
}

#define LDSM4(r0, r1, r2, r3, addr)                                        \
    asm volatile("ldmatrix.sync.aligned.m8n8.x4.shared.b16 "               \
                 "{%0,%1,%2,%3}, [%4];"                                    \
                 : "=r"(r0), "=r"(r1), "=r"(r2), "=r"(r3) : "r"(addr))

// Cheap split: hi = truncate-to-bf16 (PRMT pack), lo = round(v - hi).
__device__ __forceinline__ void bsplit2(float v0, float v1,
                                        unsigned& h, unsigned& l) {
    unsigned u0 = __float_as_uint(v0);
    unsigned u1 = __float_as_uint(v1);
    h = __byte_perm(u0, u1, 0x7632);           // {hi16(u0), hi16(u1)}
    float l0 = v0 - __uint_as_float(u0 & 0xFFFF0000u);
    float l1 = v1 - __uint_as_float(u1 & 0xFFFF0000u);
    asm("cvt.rn.bf16x2.f32 %0, %1, %2;" : "=r"(l) : "f"(l1), "f"(l0));
}

// ---------------- GEMM: xl = x @ W^T via bf16-split tensor cores ------------
// A loaded directly from global through a 4-DEEP register pipeline: each
// tile's 8 LDG.32 are issued ~4 iterations (~600 cyc) before consumption,
// so DRAM latency is covered (~3KB of sectors in flight per warp). W staged
// once per block in smem, read via ldmatrix.x4. No __syncthreads in k-loop.
__global__ void __launch_bounds__(256, 2)
k_gemm(const float* __restrict__ x, const float* __restrict__ W,
       const float* __restrict__ att_src, const float* __restrict__ att_dst,
       int nN) {
    extern __shared__ __nv_bfloat16 bsm[];
    __nv_bfloat16* Bh = bsm;                 // [32][BST]
    __nv_bfloat16* Bl = bsm + 32 * BST;

    int tid = threadIdx.x;
    int lane = tid & 31;
    int wid = tid >> 5;
    int rbase = blockIdx.x * GROWS;

    // ---- stage all of W (hi/lo split), once ----
    for (int i = tid; i < 32 * 256; i += 256) {
        int n = i >> 8;
        int k = (i & 255) << 1;
        float w0 = (k < F_IN) ? W[n * F_IN + k] : 0.f;
        float w1 = (k + 1 < F_IN) ? W[n * F_IN + k + 1] : 0.f;
        unsigned h, l;
        bsplit2(w0, w1, h, l);
        *(unsigned*)&Bh[n * BST + k] = h;
        *(unsigned*)&Bl[n * BST + k] = l;
    }
    __syncthreads();

    // fragment coordinates (PTX m16n8k16 mapping)
    int grp = lane >> 2;               // groupID (0..7)
    int qid = lane & 3;                // thread-in-group
    int frow = wid * 16 + grp;         // local A rows frow, frow+8
    int kp = qid * 2;

    int row0 = rbase + frow;
    int row1 = row0 + 8;
    const float* rp0 = x + (size_t)min(row0, nN - 1) * F_IN + kp;
    const float* rp1 = x + (size_t)min(row1, nN - 1) * F_IN + kp;

    // ldmatrix lane->address mapping
    int mrow = (lane & 7) + ((lane >> 4) << 3);
    int mcol = ((lane >> 3) & 1) << 3;
    unsigned bh_a = (unsigned)__cvta_generic_to_shared(&Bh[mrow * BST + mcol]);
    unsigned bl_a = (unsigned)__cvta_generic_to_shared(&Bl[mrow * BST + mcol]);
    const unsigned half2off = 16 * BST * 2;   // bytes to n-rows 16-31

    float c[4][4];
    #pragma unroll
    for (int nt = 0; nt < 4; nt++)
        #pragma unroll
        for (int j = 0; j < 4; j++) c[nt][j] = 0.f;

    // A-tile loader: v = {r0:k,k+1, r1:k,k+1, r0:k+8,k+9, r1:k+8,k+9}
    auto loadA = [&](int kt, float* v) {
        if (kt < 496) {
            v[0] = rp0[kt];     v[1] = rp0[kt + 1];
            v[2] = rp1[kt];     v[3] = rp1[kt + 1];
            v[4] = rp0[kt + 8]; v[5] = rp0[kt + 9];
            v[6] = rp1[kt + 8]; v[7] = rp1[kt + 9];
        } else {
            int k0 = kt + kp, k1 = kt + kp + 8;
            v[0] = (k0 < F_IN)     ? rp0[kt]     : 0.f;
            v[1] = (k0 + 1 < F_IN) ? rp0[kt + 1] : 0.f;
            v[2] = (k0 < F_IN)     ? rp1[kt]     : 0.f;
            v[3] = (k0 + 1 < F_IN) ? rp1[kt + 1] : 0.f;
            v[4] = (k1 < F_IN)     ? rp0[kt + 8] : 0.f;
            v[5] = (k1 + 1 < F_IN) ? rp0[kt + 9] : 0.f;
            v[6] = (k1 < F_IN)     ? rp1[kt + 8] : 0.f;
            v[7] = (k1 + 1 < F_IN) ? rp1[kt + 9] : 0.f;
        }
    };

    // 4-deep register pipeline
    float buf[4][8];
    loadA(0,  buf[0]);
    loadA(16, buf[1]);
    loadA(32, buf[2]);
    loadA(48, buf[3]);

    #pragma unroll 4
    for (int kt = 0; kt < 512; kt += 16) {
        const int st = (kt >> 4) & 3;   // constant within each unrolled body

        // ---- consume current tile: split to bf16 hi/lo ----
        unsigned ah[4], al[4];
        bsplit2(buf[st][0], buf[st][1], ah[0], al[0]);
        bsplit2(buf[st][2], buf[st][3], ah[1], al[1]);
        bsplit2(buf[st][4], buf[st][5], ah[2], al[2]);
        bsplit2(buf[st][6], buf[st][7], ah[3], al[3]);

        // ---- refill slot with tile kt+64 (8 independent LDG.32) ----
        if (kt < 448) loadA(kt + 64, buf[st]);

        // ---- B fragments via ldmatrix.x4 ----
        unsigned bh[8], bl[8];
        unsigned o = kt * 2;
        LDSM4(bh[0], bh[1], bh[2], bh[3], bh_a + o);
        LDSM4(bh[4], bh[5], bh[6], bh[7], bh_a + o + half2off);
        LDSM4(bl[0], bl[1], bl[2], bl[3], bl_a + o);
        LDSM4(bl[4], bl[5], bl[6], bl[7], bl_a + o + half2off);

        #pragma unroll
        for (int nt = 0; nt < 4; nt++) {
            mma16816(c[nt], ah[0], ah[1], ah[2], ah[3],
                     bh[nt * 2], bh[nt * 2 + 1]);
            mma16816(c[nt], ah[0], ah[1], ah[2], ah[3],
                     bl[nt * 2], bl[nt * 2 + 1]);
            mma16816(c[nt], al[0], al[1], al[2], al[3],
                     bh[nt * 2], bh[nt * 2 + 1]);
        }
    }

    // ---- epilogue: store xl, fused a_src/a_dst (intra-quad reduction) ----
    float as0 = 0.f, ad0 = 0.f, as1 = 0.f, ad1 = 0.f;
    #pragma unroll
    for (int nt = 0; nt < 4; nt++) {
        int ch = nt * 8 + qid * 2;
        float s0 = att_src[ch], s1 = att_src[ch + 1];
        float d0 = att_dst[ch], d1 = att_dst[ch + 1];
        if (row0 < nN)
            *(float2*)&g_xl[(size_t)row0 * CC + ch] =
                make_float2(c[nt][0], c[nt][1]);
        if (row1 < nN)
            *(float2*)&g_xl[(size_t)row1 * CC + ch] =
                make_float2(c[nt][2], c[nt][3]);
        as0 += c[nt][0] * s0 + c[nt][1] * s1;
        ad0 += c[nt][0] * d0 + c[nt][1] * d1;
        as1 += c[nt][2] * s0 + c[nt][3] * s1;
        ad1 += c[nt][2] * d0 + c[nt][3] * d1;
    }
    #pragma unroll
    for (int o = 1; o <= 2; o <<= 1) {
        as0 += __shfl_xor_sync(0xFFFFFFFFu, as0, o);
        ad0 += __shfl_xor_sync(0xFFFFFFFFu, ad0, o);
        as1 += __shfl_xor_sync(0xFFFFFFFFu, as1, o);
        ad1 += __shfl_xor_sync(0xFFFFFFFFu, ad1, o);
    }
    if (qid == 0) {
        if (row0 < nN) { g_asrc[row0] = as0; g_adst[row0] = ad0; }
        if (row1 < nN) { g_asrc[row1] = as1; g_adst[row1] = ad1; }
    }
}

// ---------------- scan (exclusive prefix of deg -> rowptr) ------------------
__global__ void k_scan1(int nN) {
    __shared__ int sh[1024];
    int tid = threadIdx.x;
    int i = blockIdx.x * 1024 + tid;
    int v = (i < nN) ? g_deg[i] : 0;
    sh[tid] = v;
    __syncthreads();
    for (int off = 1; off < 1024; off <<= 1) {
        int t = (tid >= off) ? sh[tid - off] : 0;
        __syncthreads();
        sh[tid] += t;
        __syncthreads();
    }
    if (i < nN) g_scan[i] = sh[tid];
    if (tid == 1023) g_bsum[blockIdx.x] = sh[1023];
}

__global__ void k_scan2(int nb, int nE) {
    int run = 0;
    for (int b = 0; b < nb; b++) {
        int t = g_bsum[b];
        g_boff[b] = run;
        run += t;
    }
    g_scalars[2] = g_scalars[0] / (float)nE;   // mean edge weight
}

// rowptr[i] = edge_scan[i] + i (self-loop slot per node, pre-written here).
__global__ void k_scan3(int nN, int nE) {
    int i = blockIdx.x * blockDim.x + threadIdx.x;
    if (i < nN) {
        int ex = g_scan[i] - g_deg[i] + g_boff[i >> 10] + i;
        g_rowptr[i] = ex;
        g_cursor[i] = ex + 1;
        unsigned long long e = (unsigned long long)(unsigned)i |
            ((unsigned long long)__float_as_uint(g_scalars[2]) << 32);
        g_csr[ex] = e;
    }
    if (i == 0) g_rowptr[nN] = nN + nE;
}

// ---------------- fill CSR with packed (src, edge_weight) -------------------
__global__ void k_fill(const int* __restrict__ ei, const float* __restrict__ ew,
                       int nE) {
    int i = blockIdx.x * blockDim.x + threadIdx.x;
    if (i >= nE) return;
    int s = ei[i];
    int d = ei[nE + i];
    float w = ew[i];
    int pos = atomicAdd(&g_cursor[d], 1);
    unsigned long long e = (unsigned long long)(unsigned)s |
                           ((unsigned long long)__float_as_uint(w) << 32);
    g_csr[pos] = e;
}

// ---------------- gather: softmax-aggregate + fused heads -------------------
__global__ void __launch_bounds__(256)
k_gather(const float* __restrict__ bias_conv,
         const float* __restrict__ Wb, const float* __restrict__ bb,
         const float* __restrict__ Ww, const float* __restrict__ mask,
         float* __restrict__ out, int nN, int nE) {
    int warp = (blockIdx.x * blockDim.x + threadIdx.x) >> 5;
    int lane = threadIdx.x & 31;
    if (warp >= nN) return;
    int beg = g_rowptr[warp];
    int end = g_rowptr[warp + 1];
    float ad = g_adst[warp];
    float ke = g_scalars[1];
    float acc = 0.f, den = 0.f;

    int i = beg;
    for (; i + 4 <= end; i += 4) {
        unsigned long long e0 = g_csr[i];
        unsigned long long e1 = g_csr[i + 1];
        unsigned long long e2 = g_csr[i + 2];
        unsigned long long e3 = g_csr[i + 3];
        int s0 = (int)(unsigned)e0, s1 = (int)(unsigned)e1;
        int s2 = (int)(unsigned)e2, s3 = (int)(unsigned)e3;
        float v0 = g_xl[(size_t)s0 * CC + lane];
        float v1 = g_xl[(size_t)s1 * CC + lane];
        float v2 = g_xl[(size_t)s2 * CC + lane];
        float v3 = g_xl[(size_t)s3 * CC + lane];
        float as0 = g_asrc[s0], as1 = g_asrc[s1];
        float as2 = g_asrc[s2], as3 = g_asrc[s3];
        float a0 = fmaf(ke, __uint_as_float((unsigned)(e0 >> 32)), as0 + ad);
        float a1 = fmaf(ke, __uint_as_float((unsigned)(e1 >> 32)), as1 + ad);
        float a2 = fmaf(ke, __uint_as_float((unsigned)(e2 >> 32)), as2 + ad);
        float a3 = fmaf(ke, __uint_as_float((unsigned)(e3 >> 32)), as3 + ad);
        a0 = (a0 > 0.f) ? a0 : NEG * a0;
        a1 = (a1 > 0.f) ? a1 : NEG * a1;
        a2 = (a2 > 0.f) ? a2 : NEG * a2;
        a3 = (a3 > 0.f) ? a3 : NEG * a3;
        float x0 = __expf(a0), x1 = __expf(a1);
        float x2 = __expf(a2), x3 = __expf(a3);
        den += x0 + x1 + x2 + x3;
        acc = fmaf(x0, v0, acc);
        acc = fmaf(x1, v1, acc);
        acc = fmaf(x2, v2, acc);
        acc = fmaf(x3, v3, acc);
    }
    for (; i < end; i++) {
        unsigned long long e = g_csr[i];
        int s = (int)(unsigned)e;
        float v = g_xl[(size_t)s * CC + lane];
        float a = fmaf(ke, __uint_as_float((unsigned)(e >> 32)), g_asrc[s] + ad);
        a = (a > 0.f) ? a : NEG * a;
        float ex = __expf(a);
        den += ex;
        acc = fmaf(ex, v, acc);
    }

    float h = acc / den + bias_conv[lane];
    h = fmaxf(h, 0.f);
    float bsum = h * Wb[lane];
    float wsum = h * Ww[lane];
    #pragma unroll
    for (int o = 16; o > 0; o >>= 1) {
        bsum += __shfl_xor_sync(0xFFFFFFFFu, bsum, o);
        wsum += __shfl_xor_sync(0xFFFFFFFFu, wsum, o);
    }
    if (lane == 0) {
        g_hw[warp] = wsum;
        out[nE + warp] = (bsum + bb[0]) * mask[warp];
    }
}

// ---------------- edge output: 0.5*(hw[s]+hw[d]) + bw (vectorized) ---------
__global__ void k_edge(const int* __restrict__ ei, const float* __restrict__ bw,
                       float* __restrict__ out, int nE) {
    int q = blockIdx.x * blockDim.x + threadIdx.x;
    int nq = nE >> 2;
    float b = bw[0];
    if (q < nq) {
        int4 s4 = ((const int4*)ei)[q];
        int4 d4 = ((const int4*)(ei + nE))[q];
        float4 o;
        o.x = 0.5f * (g_hw[s4.x] + g_hw[d4.x]) + b;
        o.y = 0.5f * (g_hw[s4.y] + g_hw[d4.y]) + b;
        o.z = 0.5f * (g_hw[s4.z] + g_hw[d4.z]) + b;
        o.w = 0.5f * (g_hw[s4.w] + g_hw[d4.w]) + b;
        ((float4*)out)[q] = o;
    }
    if (q < (nE & 3)) {
        int idx = (nq << 2) + q;
        out[idx] = 0.5f * (g_hw[ei[idx]] + g_hw[ei[nE + idx]]) + b;
    }
}

// ---------------- launch ----------------------------------------------------
extern "C" void kernel_launch(void* const* d_in, const int* in_sizes, int n_in,
                              void* d_out, int out_size) {
    const float* x         = (const float*)d_in[0];
    const int*   ei        = (const int*)d_in[1];
    const float* ew        = (const float*)d_in[2];
    const float* mask      = (const float*)d_in[3];
    const float* W_src     = (const float*)d_in[4];
    const float* att_src   = (const float*)d_in[5];
    const float* att_dst   = (const float*)d_in[6];
    const float* att_edge  = (const float*)d_in[7];
    const float* W_edge    = (const float*)d_in[8];
    const float* bias_conv = (const float*)d_in[9];
    const float* Wb        = (const float*)d_in[10];
    const float* bb        = (const float*)d_in[11];
    const float* Ww        = (const float*)d_in[12];
    const float* bw        = (const float*)d_in[13];
    float* out = (float*)d_out;

    int nN = in_sizes[3];            // input_mask: [N,1]
    int nE = in_sizes[2];            // edge_weight: [E,1]

    const int bsmem = 2 * 32 * BST * 2;   // 68608 B
    cudaFuncSetAttribute((const void*)k_gemm,
                         cudaFuncAttributeMaxDynamicSharedMemorySize, bsmem);

    int nb = (nN + 1023) / 1024;
    // Order keeps k_gemm in the ncu-profiled slot (4th launch).
    k_init<<<(nN + 255) / 256, 256>>>(W_edge, att_edge, nN);
    k_deg_mean<<<2048, 256>>>(ei, ew, nE);
    k_scan1<<<nb, 1024>>>(nN);
    k_gemm<<<(nN + GROWS - 1) / GROWS, 256, bsmem>>>(x, W_src, att_src,
                                                     att_dst, nN);
    k_scan2<<<1, 1>>>(nb, nE);
    k_scan3<<<(nN + 255) / 256, 256>>>(nN, nE);
    k_fill<<<(nE + 255) / 256, 256>>>(ei, ew, nE);
    k_gather<<<(nN + 7) / 8, 256>>>(bias_conv, Wb, bb, Ww, mask, out, nN, nE);
    k_edge<<<((nE >> 2) + 255) / 256, 256>>>(ei, bw, out, nE);
}